// round 17
// baseline (speedup 1.0000x reference)
#include <cuda_runtime.h>
#include <cuda_bf16.h>
#include <cstddef>
#include <cstdint>

#define TT   1024
#define BB   64
#define FF   512          // feature dim (== 2H, both layers share K=512)
#define HH   256
#define GXN  1280         // 5*H

// ---------------- scratch (device globals; no runtime allocation) ------------
__device__ float g_y  [(size_t)TT*BB*FF];        // layer-0 output / layer-1 input (fp32)
__device__ float g_fin[(size_t)TT*BB*FF];        // layer-1 output
__device__ float g_gx [2][(size_t)TT*BB*GXN];    // per-dir input-gate projections
__device__ float g_px [2][(size_t)TT*BB*HH];     // per-dir highway projections

// bf16 split operands for projections
__device__ __nv_bfloat16 g_xh[(size_t)TT*BB*FF], g_xl[(size_t)TT*BB*FF];
__device__ __nv_bfloat16 g_yh[(size_t)TT*BB*FF], g_yl[(size_t)TT*BB*FF];
__device__ __nv_bfloat16 g_wxh[2*2*FF*GXN], g_wxl[2*2*FF*GXN];
__device__ __nv_bfloat16 g_wph[2*2*FF*HH],  g_wpl[2*2*FF*HH];

// ---------------- helpers ----------------------------------------------------
__device__ __forceinline__ void split1(float x, __nv_bfloat16& h, __nv_bfloat16& l) {
    h = __float2bfloat16(x);
    l = __float2bfloat16(x - __bfloat162float(h));
}

// transpose+split: features [b][t][512] fp32 -> xh/xl [t][b][512] bf16
__global__ void k_tin(const float* __restrict__ feat,
                      __nv_bfloat16* __restrict__ xh, __nv_bfloat16* __restrict__ xl) {
    int row = blockIdx.x;               // b*T + t
    int b = row >> 10, t = row & 1023;
    float4 v = ((const float4*)(feat + (size_t)row * FF))[threadIdx.x];
    size_t drow = ((size_t)t * BB + b) * FF + threadIdx.x * 4;
    __nv_bfloat16 h4[4], l4[4];
    split1(v.x, h4[0], l4[0]); split1(v.y, h4[1], l4[1]);
    split1(v.z, h4[2], l4[2]); split1(v.w, h4[3], l4[3]);
    *(uint2*)(xh + drow) = *(uint2*)h4;
    *(uint2*)(xl + drow) = *(uint2*)l4;
}

// generic fp32 -> bf16 hi/lo split (n4 = element count / 4)
__global__ void k_split(const float* __restrict__ in,
                        __nv_bfloat16* __restrict__ hi, __nv_bfloat16* __restrict__ lo, int n4) {
    int i = blockIdx.x * blockDim.x + threadIdx.x;
    if (i >= n4) return;
    float4 v = ((const float4*)in)[i];
    __nv_bfloat16 h4[4], l4[4];
    split1(v.x, h4[0], l4[0]); split1(v.y, h4[1], l4[1]);
    split1(v.z, h4[2], l4[2]); split1(v.w, h4[3], l4[3]);
    *(uint2*)(hi + (size_t)i * 4) = *(uint2*)h4;
    *(uint2*)(lo + (size_t)i * 4) = *(uint2*)l4;
}

// transpose: fin [t][b][512] -> out [b][t][512]
__global__ void k_tout(const float* __restrict__ fin, float* __restrict__ out) {
    int row = blockIdx.x;               // t*B + b
    int t = row >> 6, b = row & 63;
    const float4* s = (const float4*)(fin + (size_t)row * FF);
    float4* d = (float4*)(out + (((size_t)b << 10) + t) * FF);
    for (int i = threadIdx.x; i < FF / 4; i += blockDim.x) d[i] = s[i];
}

// ---------------- PTX wrappers -----------------------------------------------
__device__ __forceinline__ void ldsm_x4(uint32_t* r, uint32_t a) {
    asm volatile("ldmatrix.sync.aligned.m8n8.x4.shared.b16 {%0,%1,%2,%3}, [%4];"
        : "=r"(r[0]), "=r"(r[1]), "=r"(r[2]), "=r"(r[3]) : "r"(a));
}
__device__ __forceinline__ void ldsm_x4_t(uint32_t* r, uint32_t a) {
    asm volatile("ldmatrix.sync.aligned.m8n8.x4.trans.shared.b16 {%0,%1,%2,%3}, [%4];"
        : "=r"(r[0]), "=r"(r[1]), "=r"(r[2]), "=r"(r[3]) : "r"(a));
}
__device__ __forceinline__ void ldsm_x2_t(uint32_t* r, uint32_t a) {
    asm volatile("ldmatrix.sync.aligned.m8n8.x2.trans.shared.b16 {%0,%1}, [%2];"
        : "=r"(r[0]), "=r"(r[1]) : "r"(a));
}
__device__ __forceinline__ void mma_bf16(float* c, const uint32_t* a, const uint32_t* b) {
    asm volatile("mma.sync.aligned.m16n8k16.row.col.f32.bf16.bf16.f32 "
        "{%0,%1,%2,%3},{%4,%5,%6,%7},{%8,%9},{%0,%1,%2,%3};"
        : "+f"(c[0]), "+f"(c[1]), "+f"(c[2]), "+f"(c[3])
        : "r"(a[0]), "r"(a[1]), "r"(a[2]), "r"(a[3]), "r"(b[0]), "r"(b[1]));
}
__device__ __forceinline__ void cp16(uint32_t s, const void* g) {
    asm volatile("cp.async.cg.shared.global [%0], [%1], 16;" :: "r"(s), "l"(g));
}
#define CP_COMMIT asm volatile("cp.async.commit_group;")
#define CP_WAIT1  asm volatile("cp.async.wait_group 1;")
#define CP_WAIT0  asm volatile("cp.async.wait_group 0;")

// DSMEM helpers
__device__ __forceinline__ uint32_t mapa_sc(uint32_t a, uint32_t rank) {
    uint32_t r;
    asm("mapa.shared::cluster.u32 %0, %1, %2;" : "=r"(r) : "r"(a), "r"(rank));
    return r;
}
__device__ __forceinline__ void ldsc_v4(uint32_t* v, uint32_t a) {
    asm volatile("ld.shared::cluster.v4.u32 {%0,%1,%2,%3}, [%4];"
        : "=r"(v[0]), "=r"(v[1]), "=r"(v[2]), "=r"(v[3]) : "r"(a));
}
#define CLUSTER_ARRIVE() asm volatile("barrier.cluster.arrive.aligned;" ::: "memory")
#define CLUSTER_WAIT()   asm volatile("barrier.cluster.wait.aligned;" ::: "memory")

// ---------------- tensor-core split-bf16 GEMM (unchanged, proven) -------------
#define STG_A 10240               // 128 rows * 80B pitch
#define STG_B 8192                // 32 rows * 256B, XOR-swizzled
#define STG_SZ (2*STG_A + 2*STG_B)
#define SMEM_MMA (2*STG_SZ)       // double-buffered: 73728 B

__global__ __launch_bounds__(256)
void k_mma(const __nv_bfloat16* __restrict__ Ah, const __nv_bfloat16* __restrict__ Al,
           const __nv_bfloat16* __restrict__ Bh, const __nv_bfloat16* __restrict__ Bl,
           const float* __restrict__ bias, float* __restrict__ C, int N, int K) {
    extern __shared__ char smem[];
    uint32_t su = (uint32_t)__cvta_generic_to_shared(smem);
    int tid = threadIdx.x, lane = tid & 31, wid = tid >> 5;
    int mw = wid & 3, nw = wid >> 2;          // 4x2 warp grid
    int m0 = blockIdx.y * 128, n0 = blockIdx.x * 128;

    float acc[2][8][4];
#pragma unroll
    for (int mi = 0; mi < 2; mi++)
#pragma unroll
        for (int j = 0; j < 8; j++)
#pragma unroll
            for (int q = 0; q < 4; q++) acc[mi][j][q] = 0.f;

    auto load_stage = [&](int st, int k0) {
        uint32_t sa = su + st * STG_SZ;
#pragma unroll
        for (int hl = 0; hl < 2; hl++) {
            const __nv_bfloat16* Ap = hl ? Al : Ah;
            uint32_t sb = sa + hl * STG_A;
#pragma unroll
            for (int rep = 0; rep < 2; rep++) {
                int idx = tid + rep * 256;          // 0..511
                int r = idx >> 2, c = idx & 3;
                cp16(sb + r * 80 + c * 16, Ap + (size_t)(m0 + r) * K + k0 + c * 8);
            }
        }
#pragma unroll
        for (int hl = 0; hl < 2; hl++) {
            const __nv_bfloat16* Bp = hl ? Bl : Bh;
            uint32_t sb = sa + 2 * STG_A + hl * STG_B;
#pragma unroll
            for (int rep = 0; rep < 2; rep++) {
                int idx = tid + rep * 256;
                int k = idx >> 4, c = idx & 15;
                cp16(sb + k * 256 + ((c ^ (k & 7)) * 16),
                     Bp + (size_t)(k0 + k) * N + n0 + c * 8);
            }
        }
    };

    int NIT = K >> 5;                             // 16 for K=512
    load_stage(0, 0);
    CP_COMMIT;

    for (int it = 0; it < NIT; it++) {
        if (it + 1 < NIT) { load_stage((it + 1) & 1, (it + 1) * 32); CP_COMMIT; CP_WAIT1; }
        else              { CP_WAIT0; }
        __syncthreads();

        uint32_t sa = su + (it & 1) * STG_SZ;
#pragma unroll
        for (int kk = 0; kk < 2; kk++) {
            uint32_t ah[2][4], al[2][4];
            int arow_c = kk * 2 + (lane >> 4);
            int arow_r = (lane & 15);
#pragma unroll
            for (int mi = 0; mi < 2; mi++) {
                uint32_t ad = sa + (mw * 32 + mi * 16 + arow_r) * 80 + arow_c * 16;
                ldsm_x4(ah[mi], ad);
                ldsm_x4(al[mi], ad + STG_A);
            }
#pragma unroll
            for (int jp = 0; jp < 4; jp++) {
                int krow = kk * 16 + (lane & 15);
                int cch  = nw * 8 + jp * 2 + (lane >> 4);
                uint32_t bd = sa + 2 * STG_A + krow * 256 + ((cch ^ (krow & 7)) * 16);
                uint32_t bh[4], bl[4];
                ldsm_x4_t(bh, bd);
                ldsm_x4_t(bl, bd + STG_B);
#pragma unroll
                for (int jj = 0; jj < 2; jj++) {
#pragma unroll
                    for (int mi = 0; mi < 2; mi++) {
                        float* a4 = acc[mi][jp * 2 + jj];
                        mma_bf16(a4, ah[mi], &bh[jj * 2]);  // Ahi @ Bhi
                        mma_bf16(a4, ah[mi], &bl[jj * 2]);  // Ahi @ Blo
                        mma_bf16(a4, al[mi], &bh[jj * 2]);  // Alo @ Bhi
                    }
                }
            }
        }
        __syncthreads();
    }

#pragma unroll
    for (int mi = 0; mi < 2; mi++) {
#pragma unroll
        for (int j = 0; j < 8; j++) {
            int row = m0 + mw * 32 + mi * 16 + (lane >> 2);
            int col = n0 + nw * 64 + j * 8 + (lane & 3) * 2;
            float b0 = bias[col], b1 = bias[col + 1];
            float2 v0 = {acc[mi][j][0] + b0, acc[mi][j][1] + b1};
            float2 v1 = {acc[mi][j][2] + b0, acc[mi][j][3] + b1};
            *(float2*)(C + (size_t)row * N + col)       = v0;
            *(float2*)(C + (size_t)(row + 8) * N + col) = v1;
        }
    }
}

// ---------------- persistent CLUSTER tensor-core highway-LSTM scan -----------
// grid = 128 CTAs = 16 clusters x 8.  cid = blockIdx.x>>3: d = cid&1, bg = cid>>1
// (batch group of 8). rank r = blockIdx.x&7 owns hidden cols [r*32,(r+1)*32)
// and the Wh slice [256 k][160 n] (5 gates x 32 cols), hi/lo bf16 in smem.
// Batches are independent chains -> NO global barrier; h exchange = tiny 8x32
// slices through DSMEM + one cluster barrier per step.
// smem (bytes):
//   W_hi [256][336]  @ 0        (86016)   pitch 336 = 16*21 (conflict-free tr-ldsm)
//   W_lo [256][336]  @ 86016    (86016)
//   S_hi [16][528]   @ 172032   (8448)    A staging (rows 8..15 zero)
//   S_lo [16][528]   @ 180480   (8448)
//   OUT  [2 par][2 st][8][32]u16 @188928  (4096)   produced h slices
//   Z    [2 kh][8][170] f32     @193024   (10880)
#define RW_HI 0
#define RW_LO 86016
#define RS_HI 172032
#define RS_LO 180480
#define ROUT  188928
#define RZ    193024
#define REC_SMEM (RZ + 2*8*170*4)   // 203904

__device__ __forceinline__ float fsig(float x) {
    return __fdividef(1.f, 1.f + __expf(-x));
}
__device__ __forceinline__ float ftanhf(float x) {
    return __fdividef(2.f, 1.f + __expf(-2.f * x)) - 1.f;
}

__global__ __launch_bounds__(256, 1) __cluster_dims__(8, 1, 1)
void k_rec(const float* __restrict__ Wh_l,   // [2][256][1280] (this layer)
           const float* __restrict__ bh_l,   // [2][1280]
           const float* __restrict__ gx0, const float* __restrict__ gx1,
           const float* __restrict__ px0, const float* __restrict__ px1,
           float* __restrict__ outbuf) {     // [t][b][512] (fwd|bwd concat)
    extern __shared__ char smc[];
    uint32_t su = (uint32_t)__cvta_generic_to_shared(smc);

    int tid = threadIdx.x, lane = tid & 31, wid = tid >> 5;
    int r   = blockIdx.x & 7;                 // cluster rank = col slice
    int cid = blockIdx.x >> 3;
    int d   = cid & 1;
    int bg  = cid >> 1;                       // batch group (8 batches)
    int bgl = bg * 8;
    int kh  = wid & 1, nq = wid >> 1;         // warp: k-half, n-quarter (40 n)
    int cc  = tid & 31, bq = tid >> 5;        // gate thread: col-in-slice, batch
    int col = r * 32 + cc;
    int bb  = bgl + bq;

    const float* Wh_d = Wh_l + (size_t)d * HH * GXN;
    const float* gx = d ? gx1 : gx0;
    const float* px = d ? px1 : px0;

    // fill Wh slice hi/lo: [k][n], n = g*32 + c2  (global col = r*32 + c2)
    for (int idx = tid; idx < 256 * 160; idx += 256) {
        int k = idx / 160, n = idx % 160;
        int g = n >> 5, c2 = n & 31;
        float v = Wh_d[(size_t)k * GXN + g * HH + r * 32 + c2];
        unsigned vb = __float_as_uint(v);
        unsigned short hib = (unsigned short)(vb >> 16);            // trunc split
        float lof = v - __uint_as_float(vb & 0xFFFF0000u);
        unsigned short lob;
        asm("cvt.rn.bf16.f32 %0, %1;" : "=h"(lob) : "f"(lof));
        ((unsigned short*)(smc + RW_HI + k * 336))[n] = hib;
        ((unsigned short*)(smc + RW_LO + k * 336))[n] = lob;
    }
    // zero A staging (incl. padded rows 8..15) and both OUT parities
    for (int idx = tid * 4; idx < 16 * 528; idx += 1024) {
        *(uint32_t*)(smc + RS_HI + idx) = 0u;
        *(uint32_t*)(smc + RS_LO + idx) = 0u;
    }
    for (int idx = tid; idx < 1024; idx += 256)
        ((uint32_t*)(smc + ROUT))[idx] = 0u;
    float bh5[5];
#pragma unroll
    for (int g = 0; g < 5; g++) bh5[g] = bh_l[(size_t)d * GXN + g * HH + col];
    __syncthreads();
    CLUSTER_ARRIVE();                          // publishes zeroed OUT[0]

    // gather role: peer p = wid, row grr, 16B chunk gv
    int gp = wid, grr = (tid >> 2) & 7, gv = tid & 3;
    uint32_t peer_out = mapa_sc(su + ROUT, (uint32_t)gp);
    char* sts_hi = smc + RS_HI + grr * 528 + gp * 64 + gv * 16;
    char* sts_lo = smc + RS_LO + grr * 528 + gp * 64 + gv * 16;
    float* zb = (float*)(smc + RZ);

    float cs = 0.f;

    for (int s = 0; s < TT; s++) {
        int t = d ? (TT - 1 - s) : s;

        // prefetch gate inputs (overlaps the cluster wait)
        size_t r0 = ((size_t)t * BB + bb) * GXN;
        float gxa[5];
#pragma unroll
        for (int g = 0; g < 5; g++) gxa[g] = __ldg(gx + r0 + g * HH + col);
        float pxa = __ldg(px + ((size_t)t * BB + bb) * HH + col);

        CLUSTER_WAIT();                        // all peers' OUT[s&1] ready

        // gather h(s) slices from all 8 CTAs via DSMEM -> A staging
        {
            uint32_t po = peer_out + (s & 1) * 2048 + grr * 64 + gv * 16;
            uint32_t vh[4], vl[4];
            ldsc_v4(vh, po);
            ldsc_v4(vl, po + 1024);
            *(uint4*)sts_hi = *(uint4*)vh;
            *(uint4*)sts_lo = *(uint4*)vl;
        }
        __syncthreads();

        // mma: z[16 m][40 n @ nq] over k-half kh (3 streams)
        float acc[5][4];
#pragma unroll
        for (int jt = 0; jt < 5; jt++)
#pragma unroll
            for (int q = 0; q < 4; q++) acc[jt][q] = 0.f;

        int nch = nq * 5;                      // 16B chunk base in W row
#pragma unroll
        for (int ks8 = 0; ks8 < 8; ks8++) {
            int ks = kh * 8 + ks8;
            uint32_t ah[4], al[4];
            uint32_t aad = su + RS_HI + (lane & 15) * 528 + ks * 32 + (lane >> 4) * 16;
            ldsm_x4(ah, aad);
            ldsm_x4(al, aad + (RS_LO - RS_HI));
            uint32_t brow = su + (ks * 16 + (lane & 15)) * 336;
            uint32_t bh0[4], bl0[4], bh1[4], bl1[4], bh2[2], bl2[2];
            ldsm_x4_t(bh0, brow + RW_HI + (nch + (lane >> 4)) * 16);
            ldsm_x4_t(bl0, brow + RW_LO + (nch + (lane >> 4)) * 16);
            ldsm_x4_t(bh1, brow + RW_HI + (nch + 2 + (lane >> 4)) * 16);
            ldsm_x4_t(bl1, brow + RW_LO + (nch + 2 + (lane >> 4)) * 16);
            ldsm_x2_t(bh2, brow + RW_HI + (nch + 4) * 16);
            ldsm_x2_t(bl2, brow + RW_LO + (nch + 4) * 16);
            mma_bf16(acc[0], ah, &bh0[0]); mma_bf16(acc[0], ah, &bl0[0]); mma_bf16(acc[0], al, &bh0[0]);
            mma_bf16(acc[1], ah, &bh0[2]); mma_bf16(acc[1], ah, &bl0[2]); mma_bf16(acc[1], al, &bh0[2]);
            mma_bf16(acc[2], ah, &bh1[0]); mma_bf16(acc[2], ah, &bl1[0]); mma_bf16(acc[2], al, &bh1[0]);
            mma_bf16(acc[3], ah, &bh1[2]); mma_bf16(acc[3], ah, &bl1[2]); mma_bf16(acc[3], al, &bh1[2]);
            mma_bf16(acc[4], ah, &bh2[0]); mma_bf16(acc[4], ah, &bl2[0]); mma_bf16(acc[4], al, &bh2[0]);
        }

        // z store (rows 0..7 real; c2/c3 rows 8..15 discarded)
        {
            float* zp = zb + kh * (8 * 170);
            int row = lane >> 2, c0 = (lane & 3) * 2;
#pragma unroll
            for (int jt = 0; jt < 5; jt++)
                *(float2*)&zp[row * 170 + nq * 40 + jt * 8 + c0] =
                    make_float2(acc[jt][0], acc[jt][1]);
        }
        __syncthreads();

        // gates for (col, bb): z split order = i, o, f, u, r
        float hf;
        {
            float z5[5];
#pragma unroll
            for (int g = 0; g < 5; g++) {
                int n = g * 32 + cc;
                z5[g] = zb[bq * 170 + n] + zb[8 * 170 + bq * 170 + n];
            }
            float zi = z5[0] + gxa[0] + bh5[0];
            float zo = z5[1] + gxa[1] + bh5[1];
            float zf = z5[2] + gxa[2] + bh5[2];
            float zu = z5[3] + gxa[3] + bh5[3];
            float zr = z5[4] + gxa[4] + bh5[4];
            cs = fsig(zi) * ftanhf(zu) + fsig(zf) * cs;
            float hhv = fsig(zo) * ftanhf(cs);
            float rg  = fsig(zr);
            hf = rg * hhv + (1.f - rg) * pxa;

            // split hf -> bf16 hi (trunc) + lo (rn), store to own OUT[(s+1)&1]
            unsigned fb = __float_as_uint(hf);
            unsigned short hib = (unsigned short)(fb >> 16);
            float lof = hf - __uint_as_float(fb & 0xFFFF0000u);
            unsigned short lob;
            asm("cvt.rn.bf16.f32 %0, %1;" : "=h"(lob) : "f"(lof));
            unsigned short* oh = (unsigned short*)(smc + ROUT + ((s + 1) & 1) * 2048);
            oh[bq * 32 + cc]       = hib;
            oh[512 + bq * 32 + cc] = lob;
        }

        CLUSTER_ARRIVE();                      // release own OUT stores

        // outbuf store off the inter-CTA critical path
        outbuf[((size_t)t * BB + bb) * FF + d * HH + col] = hf;
    }
    CLUSTER_WAIT();                            // drain final phase before exit
}

// ---------------------------- host driver ------------------------------------
extern "C" void kernel_launch(void* const* d_in, const int* in_sizes, int n_in,
                              void* d_out, int out_size) {
    (void)in_sizes; (void)n_in; (void)out_size;
    const float* feat = (const float*)d_in[0];
    const float* Wx   = (const float*)d_in[1];  // [2][2][512][1280]
    const float* bx   = (const float*)d_in[2];  // [2][2][1280]
    const float* Wh   = (const float*)d_in[3];  // [2][2][256][1280]
    const float* bh   = (const float*)d_in[4];  // [2][2][1280]
    const float* Wp   = (const float*)d_in[5];  // [2][2][512][256]
    const float* bp   = (const float*)d_in[6];  // [2][2][256]
    float* out = (float*)d_out;

    float *p_y, *p_f, *p_gx, *p_px;
    __nv_bfloat16 *p_xh, *p_xl, *p_yh, *p_yl, *p_wxh, *p_wxl, *p_wph, *p_wpl;
    cudaGetSymbolAddress((void**)&p_y,   g_y);
    cudaGetSymbolAddress((void**)&p_f,   g_fin);
    cudaGetSymbolAddress((void**)&p_gx,  g_gx);
    cudaGetSymbolAddress((void**)&p_px,  g_px);
    cudaGetSymbolAddress((void**)&p_xh,  g_xh);
    cudaGetSymbolAddress((void**)&p_xl,  g_xl);
    cudaGetSymbolAddress((void**)&p_yh,  g_yh);
    cudaGetSymbolAddress((void**)&p_yl,  g_yl);
    cudaGetSymbolAddress((void**)&p_wxh, g_wxh);
    cudaGetSymbolAddress((void**)&p_wxl, g_wxl);
    cudaGetSymbolAddress((void**)&p_wph, g_wph);
    cudaGetSymbolAddress((void**)&p_wpl, g_wpl);

    cudaFuncSetAttribute(k_rec, cudaFuncAttributeMaxDynamicSharedMemorySize, REC_SMEM);
    cudaFuncSetAttribute(k_mma, cudaFuncAttributeMaxDynamicSharedMemorySize, SMEM_MMA);

    const size_t GXSZ = (size_t)TT * BB * GXN;
    const size_t PXSZ = (size_t)TT * BB * HH;

    k_tin<<<TT * BB, 128>>>(feat, p_xh, p_xl);
    k_split<<<(2 * 2 * FF * GXN / 4 + 255) / 256, 256>>>(Wx, p_wxh, p_wxl, 2 * 2 * FF * GXN / 4);
    k_split<<<(2 * 2 * FF * HH  / 4 + 255) / 256, 256>>>(Wp, p_wph, p_wpl, 2 * 2 * FF * HH / 4);

    for (int l = 0; l < 2; l++) {
        const __nv_bfloat16* Ah = l ? p_yh : p_xh;
        const __nv_bfloat16* Al = l ? p_yl : p_xl;
        float* OUT = l ? p_f : p_y;
        for (int dd = 0; dd < 2; dd++) {
            int w = l * 2 + dd;
            k_mma<<<dim3(GXN / 128, (TT * BB) / 128), 256, SMEM_MMA>>>(
                Ah, Al, p_wxh + (size_t)w * FF * GXN, p_wxl + (size_t)w * FF * GXN,
                bx + (size_t)w * GXN, p_gx + dd * GXSZ, GXN, FF);
            k_mma<<<dim3(HH / 128, (TT * BB) / 128), 256, SMEM_MMA>>>(
                Ah, Al, p_wph + (size_t)w * FF * HH, p_wpl + (size_t)w * FF * HH,
                bp + (size_t)w * HH, p_px + dd * PXSZ, HH, FF);
        }
        k_rec<<<128, 256, REC_SMEM>>>(
            Wh + (size_t)l * 2 * HH * GXN, bh + (size_t)l * 2 * GXN,
            p_gx, p_gx + GXSZ, p_px, p_px + PXSZ, OUT);
        if (l == 0)
            k_split<<<(TT * BB * FF / 4) / 256, 256>>>(p_y, p_yh, p_yl, TT * BB * FF / 4);
    }

    k_tout<<<TT * BB, 128>>>(p_f, out);
}